// round 5
// baseline (speedup 1.0000x reference)
#include <cuda_runtime.h>
#include <cstdint>

#define NB 1024
#define NSEQ 144
#define NH 4
#define QK_SCALE 0.17677669529663687f

#define SQ_STRIDE 36   // Q/K row stride (words): bank = 4g + t4 -> conflict-free frag reads
#define SV_STRIDE 40   // V row stride: bank = 8*t4 + g -> conflict-free B-frag reads
#define SP_STRIDE 148  // P row stride: bank = 20g + t4 -> conflict-free A-frag reads

__device__ __forceinline__ unsigned f2tf(float f) {
    unsigned r;
    asm("cvt.rna.tf32.f32 %0, %1;" : "=r"(r) : "f"(f));
    return r;
}

__device__ __forceinline__ void mma_tf32(float c[4],
                                         unsigned a0, unsigned a1, unsigned a2, unsigned a3,
                                         unsigned b0, unsigned b1) {
    asm volatile(
        "mma.sync.aligned.m16n8k8.row.col.f32.tf32.tf32.f32 "
        "{%0,%1,%2,%3}, {%4,%5,%6,%7}, {%8,%9}, {%0,%1,%2,%3};"
        : "+f"(c[0]), "+f"(c[1]), "+f"(c[2]), "+f"(c[3])
        : "r"(a0), "r"(a1), "r"(a2), "r"(a3), "r"(b0), "r"(b1));
}

// One CTA per (b, h). 9 warps; warp w owns query rows [16w, 16w+16).
// S = Q*K^T*scale + mask  (tf32 mma, fp32 accum, mask preloaded into accumulators)
// softmax per row (quad shfl reduction), unnormalized P -> SMEM (tf32),
// O = P*V (tf32 mma), normalize in epilogue.
__global__ __launch_bounds__(288, 1)
void attn144_kernel(const float* __restrict__ qkv,
                    const float* __restrict__ mask,
                    float* __restrict__ out) {
    extern __shared__ unsigned smem[];
    unsigned* sQ = smem;                        // [144][36] tf32 (scaled)
    unsigned* sK = sQ + NSEQ * SQ_STRIDE;       // [144][36] tf32
    unsigned* sV = sK + NSEQ * SQ_STRIDE;       // [144][40] tf32, row = key idx, col = d
    unsigned* sP = sV + NSEQ * SV_STRIDE;       // [9][16][148] tf32 (per-warp)

    const int h    = blockIdx.x;
    const int b    = blockIdx.y;
    const int tid  = threadIdx.x;
    const int warp = tid >> 5;
    const int lane = tid & 31;
    const int g    = lane >> 2;   // groupID (row within fragment)
    const int t4   = lane & 3;    // threadID_in_group

    // qkv[b, n, j, h, d] at ((b*144+n)*384 + j*128 + h*32 + d)
    const float* base = qkv + (size_t)(b * NSEQ) * 384 + h * 32;

    // ---- Stage Q (pre-scaled), K, V into SMEM as tf32, float4 granularity ----
    for (int idx = tid; idx < NSEQ * 8; idx += 288) {
        int row = idx >> 3;
        int d4  = (idx & 7) * 4;
        const float* p = base + (size_t)row * 384 + d4;
        float4 q4 = *(const float4*)(p);
        float4 k4 = *(const float4*)(p + 128);
        float4 v4 = *(const float4*)(p + 256);
        uint4 qt = { f2tf(q4.x * QK_SCALE), f2tf(q4.y * QK_SCALE),
                     f2tf(q4.z * QK_SCALE), f2tf(q4.w * QK_SCALE) };
        uint4 kt = { f2tf(k4.x), f2tf(k4.y), f2tf(k4.z), f2tf(k4.w) };
        uint4 vt = { f2tf(v4.x), f2tf(v4.y), f2tf(v4.z), f2tf(v4.w) };
        *(uint4*)(sQ + row * SQ_STRIDE + d4) = qt;
        *(uint4*)(sK + row * SQ_STRIDE + d4) = kt;
        *(uint4*)(sV + row * SV_STRIDE + d4) = vt;
    }
    __syncthreads();

    const int row0 = warp * 16 + g;   // this thread's upper fragment row
    // ---- Preload Q A-fragments (16 regs, reused across all 18 n-tiles) ----
    unsigned a[4][4];
#pragma unroll
    for (int kt = 0; kt < 4; kt++) {
        a[kt][0] = sQ[row0 * SQ_STRIDE + kt * 8 + t4];
        a[kt][1] = sQ[(row0 + 8) * SQ_STRIDE + kt * 8 + t4];
        a[kt][2] = sQ[row0 * SQ_STRIDE + kt * 8 + t4 + 4];
        a[kt][3] = sQ[(row0 + 8) * SQ_STRIDE + kt * 8 + t4 + 4];
    }

    // ---- S = mask + Q K^T ----
    float c[18][4];
    const float* mrow0 = mask + ((size_t)h * NSEQ + row0) * NSEQ;
    const float* mrow1 = mrow0 + 8 * NSEQ;
#pragma unroll
    for (int nt = 0; nt < 18; nt++) {
        int col = nt * 8 + 2 * t4;
        float2 m0 = *(const float2*)(mrow0 + col);
        float2 m1 = *(const float2*)(mrow1 + col);
        c[nt][0] = m0.x; c[nt][1] = m0.y; c[nt][2] = m1.x; c[nt][3] = m1.y;
        const unsigned* krow = sK + (nt * 8 + g) * SQ_STRIDE;
#pragma unroll
        for (int kt = 0; kt < 4; kt++) {
            unsigned b0 = krow[kt * 8 + t4];
            unsigned b1 = krow[kt * 8 + t4 + 4];
            mma_tf32(c[nt], a[kt][0], a[kt][1], a[kt][2], a[kt][3], b0, b1);
        }
    }

    // ---- Softmax over 144 cols; each row lives in one quad (4 lanes x 36 vals) ----
    float mx0 = -1e30f, mx1 = -1e30f;
#pragma unroll
    for (int nt = 0; nt < 18; nt++) {
        mx0 = fmaxf(mx0, fmaxf(c[nt][0], c[nt][1]));
        mx1 = fmaxf(mx1, fmaxf(c[nt][2], c[nt][3]));
    }
    mx0 = fmaxf(mx0, __shfl_xor_sync(0xffffffffu, mx0, 1));
    mx0 = fmaxf(mx0, __shfl_xor_sync(0xffffffffu, mx0, 2));
    mx1 = fmaxf(mx1, __shfl_xor_sync(0xffffffffu, mx1, 1));
    mx1 = fmaxf(mx1, __shfl_xor_sync(0xffffffffu, mx1, 2));

    float s0 = 0.f, s1 = 0.f;
#pragma unroll
    for (int nt = 0; nt < 18; nt++) {
        c[nt][0] = __expf(c[nt][0] - mx0);
        c[nt][1] = __expf(c[nt][1] - mx0);
        c[nt][2] = __expf(c[nt][2] - mx1);
        c[nt][3] = __expf(c[nt][3] - mx1);
        s0 += c[nt][0] + c[nt][1];
        s1 += c[nt][2] + c[nt][3];
    }
    s0 += __shfl_xor_sync(0xffffffffu, s0, 1);
    s0 += __shfl_xor_sync(0xffffffffu, s0, 2);
    s1 += __shfl_xor_sync(0xffffffffu, s1, 1);
    s1 += __shfl_xor_sync(0xffffffffu, s1, 2);
    const float inv0 = 1.f / s0;
    const float inv1 = 1.f / s1;

    // ---- Write unnormalized P (tf32) to per-warp SMEM tile (C->A relayout) ----
    unsigned* pw = sP + warp * 16 * SP_STRIDE;
#pragma unroll
    for (int nt = 0; nt < 18; nt++) {
        int col = nt * 8 + 2 * t4;
        pw[g * SP_STRIDE + col]           = f2tf(c[nt][0]);
        pw[g * SP_STRIDE + col + 1]       = f2tf(c[nt][1]);
        pw[(g + 8) * SP_STRIDE + col]     = f2tf(c[nt][2]);
        pw[(g + 8) * SP_STRIDE + col + 1] = f2tf(c[nt][3]);
    }
    __syncwarp();

    // ---- O = P V ----
    float o[4][4];
#pragma unroll
    for (int nt2 = 0; nt2 < 4; nt2++) {
        o[nt2][0] = 0.f; o[nt2][1] = 0.f; o[nt2][2] = 0.f; o[nt2][3] = 0.f;
    }
#pragma unroll
    for (int kt = 0; kt < 18; kt++) {
        unsigned pa0 = pw[g * SP_STRIDE + kt * 8 + t4];
        unsigned pa1 = pw[(g + 8) * SP_STRIDE + kt * 8 + t4];
        unsigned pa2 = pw[g * SP_STRIDE + kt * 8 + t4 + 4];
        unsigned pa3 = pw[(g + 8) * SP_STRIDE + kt * 8 + t4 + 4];
        const unsigned* v0 = sV + (kt * 8 + t4) * SV_STRIDE;
        const unsigned* v1 = sV + (kt * 8 + t4 + 4) * SV_STRIDE;
#pragma unroll
        for (int nt2 = 0; nt2 < 4; nt2++) {
            unsigned b0 = v0[nt2 * 8 + g];
            unsigned b1 = v1[nt2 * 8 + g];
            mma_tf32(o[nt2], pa0, pa1, pa2, pa3, b0, b1);
        }
    }

    // ---- Normalize + store: out[b, n, h*32 + d] ----
    float* obase = out + ((size_t)b * NSEQ + row0) * 128 + h * 32;
#pragma unroll
    for (int nt2 = 0; nt2 < 4; nt2++) {
        int col = nt2 * 8 + 2 * t4;
        float2 r0 = { o[nt2][0] * inv0, o[nt2][1] * inv0 };
        float2 r1 = { o[nt2][2] * inv1, o[nt2][3] * inv1 };
        *(float2*)(obase + col)            = r0;
        *(float2*)(obase + 8 * 128 + col)  = r1;
    }
}

extern "C" void kernel_launch(void* const* d_in, const int* in_sizes, int n_in,
                              void* d_out, int out_size) {
    const float* qkv  = (const float*)d_in[0];
    const float* mask = (const float*)d_in[1];
    float* out = (float*)d_out;

    const int smem_bytes =
        (NSEQ * SQ_STRIDE * 2 + NSEQ * SV_STRIDE + 9 * 16 * SP_STRIDE) * 4;  // 149,760 B

    cudaFuncSetAttribute(attn144_kernel,
                         cudaFuncAttributeMaxDynamicSharedMemorySize, smem_bytes);

    dim3 grid(NH, NB);
    attn144_kernel<<<grid, 288, smem_bytes>>>(qkv, mask, out);
}

// round 7
// speedup vs baseline: 1.5450x; 1.5450x over previous
#include <cuda_runtime.h>
#include <cstdint>

#define NB 1024
#define NSEQ 144
#define NH 4
#define QK_SCALE 0.17677669529663687f

#define SQ_STRIDE 36   // Q/K row stride (words): bank = 4g + t4 -> conflict-free frag reads
#define SV_STRIDE 40   // V row stride: bank = 8*t4 + g -> conflict-free B-frag reads
#define SP_STRIDE 52   // P chunk row stride: bank = 20g + t4 -> conflict-free A-frag reads
#define CHUNK_T 6      // k-tiles per PV chunk (48 cols); 3 chunks cover 144

__device__ __forceinline__ unsigned f2tf(float f) {
    unsigned r;
    asm("cvt.rna.tf32.f32 %0, %1;" : "=r"(r) : "f"(f));
    return r;
}

__device__ __forceinline__ void mma_tf32(float c[4],
                                         unsigned a0, unsigned a1, unsigned a2, unsigned a3,
                                         unsigned b0, unsigned b1) {
    asm volatile(
        "mma.sync.aligned.m16n8k8.row.col.f32.tf32.tf32.f32 "
        "{%0,%1,%2,%3}, {%4,%5,%6,%7}, {%8,%9}, {%0,%1,%2,%3};"
        : "+f"(c[0]), "+f"(c[1]), "+f"(c[2]), "+f"(c[3])
        : "r"(a0), "r"(a1), "r"(a2), "r"(a3), "r"(b0), "r"(b1));
}

// One CTA per (b, h), 2 CTAs/SM. 9 warps; warp w owns query rows [16w, 16w+16).
// Staging: LDG float4 -> cvt.rna.tf32 -> STS (unbiased rounding; mma-side
// truncation of raw fp32 was measured at rel_err 1.07e-3 -> fails).
// S = Q*K^T*scale + mask (mask preloaded into accumulators),
// softmax per row (quad shfl), unnormalized P -> per-warp SMEM chunk -> PV mma,
// 3 chunks, normalize in epilogue.
__global__ __launch_bounds__(288, 2)
void attn144_kernel(const float* __restrict__ qkv,
                    const float* __restrict__ mask,
                    float* __restrict__ out) {
    extern __shared__ unsigned smem[];
    unsigned* sQ = smem;                        // [144][36] tf32 (pre-scaled)
    unsigned* sK = sQ + NSEQ * SQ_STRIDE;       // [144][36] tf32
    unsigned* sV = sK + NSEQ * SQ_STRIDE;       // [144][40] tf32, row = key idx, col = d
    unsigned* sP = sV + NSEQ * SV_STRIDE;       // [9][16][52] tf32 per-warp chunk

    const int h    = blockIdx.x;
    const int b    = blockIdx.y;
    const int tid  = threadIdx.x;
    const int warp = tid >> 5;
    const int lane = tid & 31;
    const int g    = lane >> 2;   // groupID (row within fragment)
    const int t4   = lane & 3;    // threadID_in_group

    // qkv[b, n, j, h, d] at ((b*144+n)*384 + j*128 + h*32 + d)
    const float* base = qkv + (size_t)(b * NSEQ) * 384 + h * 32;

    // ---- Stage Q (pre-scaled), K, V as tf32 (rna-rounded), float4 granularity ----
#pragma unroll
    for (int it = 0; it < 4; it++) {
        int idx = tid + it * 288;
        int row = idx >> 3;
        int d4  = (idx & 7) * 4;
        const float* p = base + (size_t)row * 384 + d4;
        float4 q4 = *(const float4*)(p);
        float4 k4 = *(const float4*)(p + 128);
        float4 v4 = *(const float4*)(p + 256);
        uint4 qt = { f2tf(q4.x * QK_SCALE), f2tf(q4.y * QK_SCALE),
                     f2tf(q4.z * QK_SCALE), f2tf(q4.w * QK_SCALE) };
        uint4 kt = { f2tf(k4.x), f2tf(k4.y), f2tf(k4.z), f2tf(k4.w) };
        uint4 vt = { f2tf(v4.x), f2tf(v4.y), f2tf(v4.z), f2tf(v4.w) };
        *(uint4*)(sQ + row * SQ_STRIDE + d4) = qt;
        *(uint4*)(sK + row * SQ_STRIDE + d4) = kt;
        *(uint4*)(sV + row * SV_STRIDE + d4) = vt;
    }

    const int row0 = warp * 16 + g;   // this thread's upper fragment row

    // ---- Preload mask into S accumulators (LDGs overlap the staging stores) ----
    float c[18][4];
    const float* mrow0 = mask + ((size_t)h * NSEQ + row0) * NSEQ;
    const float* mrow1 = mrow0 + 8 * NSEQ;
#pragma unroll
    for (int nt = 0; nt < 18; nt++) {
        int col = nt * 8 + 2 * t4;
        float2 m0 = *(const float2*)(mrow0 + col);
        float2 m1 = *(const float2*)(mrow1 + col);
        c[nt][0] = m0.x; c[nt][1] = m0.y; c[nt][2] = m1.x; c[nt][3] = m1.y;
    }
    __syncthreads();

    // ---- S += Q K^T  (kt outer: only 4 Q regs live at a time) ----
#pragma unroll
    for (int kt = 0; kt < 4; kt++) {
        const unsigned* q0 = sQ + row0 * SQ_STRIDE + kt * 8;
        const unsigned* q1 = sQ + (row0 + 8) * SQ_STRIDE + kt * 8;
        unsigned a0 = q0[t4];
        unsigned a1 = q1[t4];
        unsigned a2 = q0[t4 + 4];
        unsigned a3 = q1[t4 + 4];
#pragma unroll
        for (int nt = 0; nt < 18; nt++) {
            const unsigned* krow = sK + (nt * 8 + g) * SQ_STRIDE + kt * 8;
            mma_tf32(c[nt], a0, a1, a2, a3, krow[t4], krow[t4 + 4]);
        }
    }

    // ---- Softmax over 144 cols; each row lives in one quad (4 lanes x 36 vals) ----
    float mx0 = -1e30f, mx1 = -1e30f;
#pragma unroll
    for (int nt = 0; nt < 18; nt++) {
        mx0 = fmaxf(mx0, fmaxf(c[nt][0], c[nt][1]));
        mx1 = fmaxf(mx1, fmaxf(c[nt][2], c[nt][3]));
    }
    mx0 = fmaxf(mx0, __shfl_xor_sync(0xffffffffu, mx0, 1));
    mx0 = fmaxf(mx0, __shfl_xor_sync(0xffffffffu, mx0, 2));
    mx1 = fmaxf(mx1, __shfl_xor_sync(0xffffffffu, mx1, 1));
    mx1 = fmaxf(mx1, __shfl_xor_sync(0xffffffffu, mx1, 2));

    float s0 = 0.f, s1 = 0.f;
#pragma unroll
    for (int nt = 0; nt < 18; nt++) {
        c[nt][0] = __expf(c[nt][0] - mx0);
        c[nt][1] = __expf(c[nt][1] - mx0);
        c[nt][2] = __expf(c[nt][2] - mx1);
        c[nt][3] = __expf(c[nt][3] - mx1);
        s0 += c[nt][0] + c[nt][1];
        s1 += c[nt][2] + c[nt][3];
    }
    s0 += __shfl_xor_sync(0xffffffffu, s0, 1);
    s0 += __shfl_xor_sync(0xffffffffu, s0, 2);
    s1 += __shfl_xor_sync(0xffffffffu, s1, 1);
    s1 += __shfl_xor_sync(0xffffffffu, s1, 2);
    const float inv0 = 1.f / s0;
    const float inv1 = 1.f / s1;

    // ---- O = P V, chunked through per-warp SMEM tile (C->A relayout) ----
    float o[4][4];
#pragma unroll
    for (int nt2 = 0; nt2 < 4; nt2++) {
        o[nt2][0] = 0.f; o[nt2][1] = 0.f; o[nt2][2] = 0.f; o[nt2][3] = 0.f;
    }
    unsigned* pw = sP + warp * 16 * SP_STRIDE;
#pragma unroll
    for (int ch = 0; ch < 3; ch++) {
        // write unnormalized P chunk (tf32 rna, v2 stores)
#pragma unroll
        for (int j = 0; j < CHUNK_T; j++) {
            int nt  = ch * CHUNK_T + j;
            int col = j * 8 + 2 * t4;
            uint2 lo = { f2tf(c[nt][0]), f2tf(c[nt][1]) };
            uint2 hi = { f2tf(c[nt][2]), f2tf(c[nt][3]) };
            *(uint2*)(pw + g * SP_STRIDE + col)       = lo;
            *(uint2*)(pw + (g + 8) * SP_STRIDE + col) = hi;
        }
        __syncwarp();
#pragma unroll
        for (int j = 0; j < CHUNK_T; j++) {
            int ktg = ch * CHUNK_T + j;
            unsigned pa0 = pw[g * SP_STRIDE + j * 8 + t4];
            unsigned pa1 = pw[(g + 8) * SP_STRIDE + j * 8 + t4];
            unsigned pa2 = pw[g * SP_STRIDE + j * 8 + t4 + 4];
            unsigned pa3 = pw[(g + 8) * SP_STRIDE + j * 8 + t4 + 4];
            const unsigned* v0 = sV + (ktg * 8 + t4) * SV_STRIDE;
            const unsigned* v1 = sV + (ktg * 8 + t4 + 4) * SV_STRIDE;
#pragma unroll
            for (int nt2 = 0; nt2 < 4; nt2++) {
                mma_tf32(o[nt2], pa0, pa1, pa2, pa3, v0[nt2 * 8 + g], v1[nt2 * 8 + g]);
            }
        }
        __syncwarp();   // chunk buffer reused next iteration
    }

    // ---- Normalize + store: out[b, n, h*32 + d] ----
    float* obase = out + ((size_t)b * NSEQ + row0) * 128 + h * 32;
#pragma unroll
    for (int nt2 = 0; nt2 < 4; nt2++) {
        int col = nt2 * 8 + 2 * t4;
        float2 r0 = { o[nt2][0] * inv0, o[nt2][1] * inv0 };
        float2 r1 = { o[nt2][2] * inv1, o[nt2][3] * inv1 };
        *(float2*)(obase + col)           = r0;
        *(float2*)(obase + 8 * 128 + col) = r1;
    }
}

extern "C" void kernel_launch(void* const* d_in, const int* in_sizes, int n_in,
                              void* d_out, int out_size) {
    const float* qkv  = (const float*)d_in[0];
    const float* mask = (const float*)d_in[1];
    float* out = (float*)d_out;

    const int smem_bytes =
        (NSEQ * SQ_STRIDE * 2 + NSEQ * SV_STRIDE + 9 * 16 * SP_STRIDE) * 4;  // 94,464 B

    cudaFuncSetAttribute(attn144_kernel,
                         cudaFuncAttributeMaxDynamicSharedMemorySize, smem_bytes);

    dim3 grid(NH, NB);
    attn144_kernel<<<grid, 288, smem_bytes>>>(qkv, mask, out);
}

// round 8
// speedup vs baseline: 2.2365x; 1.4475x over previous
#include <cuda_runtime.h>
#include <cuda_fp16.h>
#include <cstdint>

#define NB 1024
#define NSEQ 144
#define NH 4
#define QK_SCALE 0.17677669529663687f

#define SKW 20   // K row stride (f16x2 words): 16 data + 4 pad -> bank 20g+t4+8kt permutation
#define SVW 76   // V^T row stride (f16x2 words): 72 data + 4 pad -> bank 12d+8j+t4 permutation

__device__ __forceinline__ unsigned pack_h2(float lo, float hi) {
    __half2 hv = __floats2half2_rn(lo, hi);   // x = lo half, y = hi half
    return *reinterpret_cast<unsigned*>(&hv);
}

__device__ __forceinline__ void mma_f16(float c[4],
                                        unsigned a0, unsigned a1, unsigned a2, unsigned a3,
                                        unsigned b0, unsigned b1) {
    asm volatile(
        "mma.sync.aligned.m16n8k16.row.col.f32.f16.f16.f32 "
        "{%0,%1,%2,%3}, {%4,%5,%6,%7}, {%8,%9}, {%0,%1,%2,%3};"
        : "+f"(c[0]), "+f"(c[1]), "+f"(c[2]), "+f"(c[3])
        : "r"(a0), "r"(a1), "r"(a2), "r"(a3), "r"(b0), "r"(b1));
}

// One CTA per (b,h), 2 CTAs/SM, 9 warps, warp w owns query rows [16w, 16w+16).
// fp16 mma (f32 accum; fp16 mantissa == tf32 mantissa, so numerics match R7).
// Q: direct coalesced LDG.64 A-fragments (no smem; each element read once).
// K: smem row-major f16x2 along d. V: smem transposed, f16x2 along keys.
// P: C-fragment == fp16 A-fragment layout -> pure register pack, NO smem round trip.
__global__ __launch_bounds__(288, 2)
void attn144_kernel(const float* __restrict__ qkv,
                    const float* __restrict__ mask,
                    float* __restrict__ out) {
    __shared__ unsigned sK[NSEQ * SKW];   // [144][20] f16x2: word (row, d/2)
    __shared__ unsigned sV[32 * SVW];     // [32][76] f16x2: word (d, key/2)

    const int h    = blockIdx.x;
    const int b    = blockIdx.y;
    const int tid  = threadIdx.x;
    const int warp = tid >> 5;
    const int lane = tid & 31;
    const int g    = lane >> 2;
    const int t4   = lane & 3;

    // qkv[b, n, j, h, d] at ((b*144+n)*384 + j*128 + h*32 + d)
    const float* base = qkv + (size_t)(b * NSEQ) * 384 + h * 32;

    // ---- Stage K (f16x2 along d) and V^T (f16x2 along keys, lane^8 pair interleave) ----
#pragma unroll
    for (int it = 0; it < 4; it++) {
        int idx = tid + it * 288;
        int row = idx >> 3;          // key index
        int d4  = (idx & 7) * 4;     // head-dim base
        const float* p = base + (size_t)row * 384 + d4;
        float4 k4 = *(const float4*)(p + 128);
        float4 v4 = *(const float4*)(p + 256);

        unsigned k01 = pack_h2(k4.x, k4.y);
        unsigned k23 = pack_h2(k4.z, k4.w);
        *(uint2*)(sK + row * SKW + (d4 >> 1)) = make_uint2(k01, k23);

        unsigned v01 = pack_h2(v4.x, v4.y);
        unsigned v23 = pack_h2(v4.z, v4.w);
        // partner lane (^8) holds key^1 at same d4
        unsigned pv01 = __shfl_xor_sync(0xffffffffu, v01, 8);
        unsigned pv23 = __shfl_xor_sync(0xffffffffu, v23, 8);
        int kw = row >> 1;
        if (!(idx & 8)) {  // even key: I am the lo half of each pair
            sV[(d4    ) * SVW + kw] = __byte_perm(v01, pv01, 0x5410);
            sV[(d4 + 1) * SVW + kw] = __byte_perm(v01, pv01, 0x7632);
        } else {           // odd key: partner (even key) is the lo half
            sV[(d4 + 2) * SVW + kw] = __byte_perm(pv23, v23, 0x5410);
            sV[(d4 + 3) * SVW + kw] = __byte_perm(pv23, v23, 0x7632);
        }
    }

    const int row0 = warp * 16 + g;

    // ---- Preload mask into S accumulators (overlaps staging stores) ----
    float c[18][4];
    const float* mrow0 = mask + ((size_t)h * NSEQ + row0) * NSEQ;
    const float* mrow1 = mrow0 + 8 * NSEQ;
#pragma unroll
    for (int nt = 0; nt < 18; nt++) {
        int col = nt * 8 + 2 * t4;
        float2 m0 = *(const float2*)(mrow0 + col);
        float2 m1 = *(const float2*)(mrow1 + col);
        c[nt][0] = m0.x; c[nt][1] = m0.y; c[nt][2] = m1.x; c[nt][3] = m1.y;
    }

    // ---- Q A-fragments straight from GMEM (fully coalesced, zero smem) ----
    unsigned a[2][4];
    const float* q0p = base + (size_t)row0 * 384;
    const float* q1p = q0p + 8 * 384;
#pragma unroll
    for (int kt = 0; kt < 2; kt++) {
        float2 q00 = *(const float2*)(q0p + kt * 16 + 2 * t4);
        float2 q10 = *(const float2*)(q1p + kt * 16 + 2 * t4);
        float2 q01 = *(const float2*)(q0p + kt * 16 + 2 * t4 + 8);
        float2 q11 = *(const float2*)(q1p + kt * 16 + 2 * t4 + 8);
        a[kt][0] = pack_h2(q00.x * QK_SCALE, q00.y * QK_SCALE);
        a[kt][1] = pack_h2(q10.x * QK_SCALE, q10.y * QK_SCALE);
        a[kt][2] = pack_h2(q01.x * QK_SCALE, q01.y * QK_SCALE);
        a[kt][3] = pack_h2(q11.x * QK_SCALE, q11.y * QK_SCALE);
    }
    __syncthreads();

    // ---- S = mask + Q K^T  (36 mmas) ----
#pragma unroll
    for (int kt = 0; kt < 2; kt++) {
#pragma unroll
        for (int nt = 0; nt < 18; nt++) {
            const unsigned* kr = sK + (nt * 8 + g) * SKW + kt * 8;
            mma_f16(c[nt], a[kt][0], a[kt][1], a[kt][2], a[kt][3], kr[t4], kr[t4 + 4]);
        }
    }

    // ---- Softmax over 144 cols (each row in one quad) ----
    float mx0 = -1e30f, mx1 = -1e30f;
#pragma unroll
    for (int nt = 0; nt < 18; nt++) {
        mx0 = fmaxf(mx0, fmaxf(c[nt][0], c[nt][1]));
        mx1 = fmaxf(mx1, fmaxf(c[nt][2], c[nt][3]));
    }
    mx0 = fmaxf(mx0, __shfl_xor_sync(0xffffffffu, mx0, 1));
    mx0 = fmaxf(mx0, __shfl_xor_sync(0xffffffffu, mx0, 2));
    mx1 = fmaxf(mx1, __shfl_xor_sync(0xffffffffu, mx1, 1));
    mx1 = fmaxf(mx1, __shfl_xor_sync(0xffffffffu, mx1, 2));

    float s0 = 0.f, s1 = 0.f;
#pragma unroll
    for (int nt = 0; nt < 18; nt++) {
        c[nt][0] = __expf(c[nt][0] - mx0);
        c[nt][1] = __expf(c[nt][1] - mx0);
        c[nt][2] = __expf(c[nt][2] - mx1);
        c[nt][3] = __expf(c[nt][3] - mx1);
        s0 += c[nt][0] + c[nt][1];
        s1 += c[nt][2] + c[nt][3];
    }
    s0 += __shfl_xor_sync(0xffffffffu, s0, 1);
    s0 += __shfl_xor_sync(0xffffffffu, s0, 2);
    s1 += __shfl_xor_sync(0xffffffffu, s1, 1);
    s1 += __shfl_xor_sync(0xffffffffu, s1, 2);
    const float inv0 = 1.f / s0;
    const float inv1 = 1.f / s1;

    // ---- O = P V: C-frag -> fp16 A-frag by register pack (36 mmas, no smem P) ----
    float o[4][4];
#pragma unroll
    for (int nt2 = 0; nt2 < 4; nt2++) {
        o[nt2][0] = 0.f; o[nt2][1] = 0.f; o[nt2][2] = 0.f; o[nt2][3] = 0.f;
    }
#pragma unroll
    for (int j = 0; j < 9; j++) {
        unsigned pa0 = pack_h2(c[2 * j][0],     c[2 * j][1]);
        unsigned pa1 = pack_h2(c[2 * j][2],     c[2 * j][3]);
        unsigned pa2 = pack_h2(c[2 * j + 1][0], c[2 * j + 1][1]);
        unsigned pa3 = pack_h2(c[2 * j + 1][2], c[2 * j + 1][3]);
#pragma unroll
        for (int nt2 = 0; nt2 < 4; nt2++) {
            const unsigned* vr = sV + (nt2 * 8 + g) * SVW + j * 8;
            mma_f16(o[nt2], pa0, pa1, pa2, pa3, vr[t4], vr[t4 + 4]);
        }
    }

    // ---- Normalize + store: out[b, n, h*32 + d] ----
    float* obase = out + ((size_t)b * NSEQ + row0) * 128 + h * 32;
#pragma unroll
    for (int nt2 = 0; nt2 < 4; nt2++) {
        int col = nt2 * 8 + 2 * t4;
        float2 r0 = { o[nt2][0] * inv0, o[nt2][1] * inv0 };
        float2 r1 = { o[nt2][2] * inv1, o[nt2][3] * inv1 };
        *(float2*)(obase + col)           = r0;
        *(float2*)(obase + 8 * 128 + col) = r1;
    }
}

extern "C" void kernel_launch(void* const* d_in, const int* in_sizes, int n_in,
                              void* d_out, int out_size) {
    const float* qkv  = (const float*)d_in[0];
    const float* mask = (const float*)d_in[1];
    float* out = (float*)d_out;

    dim3 grid(NH, NB);
    attn144_kernel<<<grid, 288>>>(qkv, mask, out);
}

// round 9
// speedup vs baseline: 2.2586x; 1.0099x over previous
#include <cuda_runtime.h>
#include <cuda_fp16.h>
#include <cstdint>

#define NB 1024
#define NSEQ 144
#define NH 4
#define QK_SCALE 0.17677669529663687f

#define SKW 20   // K row stride (f16x2 words): 16 data + 4 pad -> bank 20g+t4+8kt permutation
#define SVW 76   // V^T row stride (f16x2 words): 72 data + 4 pad -> bank 12d+8j+t4 permutation

__device__ __forceinline__ unsigned pack_h2(float lo, float hi) {
    __half2 hv = __floats2half2_rn(lo, hi);   // x = lo half, y = hi half
    return *reinterpret_cast<unsigned*>(&hv);
}

__device__ __forceinline__ void mma_f16(float c[4],
                                        unsigned a0, unsigned a1, unsigned a2, unsigned a3,
                                        unsigned b0, unsigned b1) {
    asm volatile(
        "mma.sync.aligned.m16n8k16.row.col.f32.f16.f16.f32 "
        "{%0,%1,%2,%3}, {%4,%5,%6,%7}, {%8,%9}, {%0,%1,%2,%3};"
        : "+f"(c[0]), "+f"(c[1]), "+f"(c[2]), "+f"(c[3])
        : "r"(a0), "r"(a1), "r"(a2), "r"(a3), "r"(b0), "r"(b1));
}

// One CTA per (b,h), 2 CTAs/SM, 9 warps, warp w owns query rows [16w, 16w+16).
// fp16 mma (f32 accum; fp16 mantissa == tf32 mantissa, so numerics match R7).
// Q: direct coalesced LDG.64 A-fragments (no smem; each element read once).
// K: smem row-major f16x2 along d. V: smem transposed, f16x2 along keys.
// P: C-fragment == fp16 A-fragment layout -> pure register pack, NO smem round trip.
__global__ __launch_bounds__(288, 2)
void attn144_kernel(const float* __restrict__ qkv,
                    const float* __restrict__ mask,
                    float* __restrict__ out) {
    __shared__ unsigned sK[NSEQ * SKW];   // [144][20] f16x2: word (row, d/2)
    __shared__ unsigned sV[32 * SVW];     // [32][76] f16x2: word (d, key/2)

    const int h    = blockIdx.x;
    const int b    = blockIdx.y;
    const int tid  = threadIdx.x;
    const int warp = tid >> 5;
    const int lane = tid & 31;
    const int g    = lane >> 2;
    const int t4   = lane & 3;

    // qkv[b, n, j, h, d] at ((b*144+n)*384 + j*128 + h*32 + d)
    const float* base = qkv + (size_t)(b * NSEQ) * 384 + h * 32;

    // ---- Stage K (f16x2 along d) and V^T (f16x2 along keys, lane^8 pair interleave) ----
#pragma unroll
    for (int it = 0; it < 4; it++) {
        int idx = tid + it * 288;
        int row = idx >> 3;          // key index
        int d4  = (idx & 7) * 4;     // head-dim base
        const float* p = base + (size_t)row * 384 + d4;
        float4 k4 = *(const float4*)(p + 128);
        float4 v4 = *(const float4*)(p + 256);

        unsigned k01 = pack_h2(k4.x, k4.y);
        unsigned k23 = pack_h2(k4.z, k4.w);
        *(uint2*)(sK + row * SKW + (d4 >> 1)) = make_uint2(k01, k23);

        unsigned v01 = pack_h2(v4.x, v4.y);
        unsigned v23 = pack_h2(v4.z, v4.w);
        // partner lane (^8) holds key^1 at same d4
        unsigned pv01 = __shfl_xor_sync(0xffffffffu, v01, 8);
        unsigned pv23 = __shfl_xor_sync(0xffffffffu, v23, 8);
        int kw = row >> 1;
        if (!(idx & 8)) {  // even key: I am the lo half of each pair
            sV[(d4    ) * SVW + kw] = __byte_perm(v01, pv01, 0x5410);
            sV[(d4 + 1) * SVW + kw] = __byte_perm(v01, pv01, 0x7632);
        } else {           // odd key: partner (even key) is the lo half
            sV[(d4 + 2) * SVW + kw] = __byte_perm(pv23, v23, 0x5410);
            sV[(d4 + 3) * SVW + kw] = __byte_perm(pv23, v23, 0x7632);
        }
    }

    const int row0 = warp * 16 + g;

    // ---- Preload mask into S accumulators (overlaps staging stores) ----
    float c[18][4];
    const float* mrow0 = mask + ((size_t)h * NSEQ + row0) * NSEQ;
    const float* mrow1 = mrow0 + 8 * NSEQ;
#pragma unroll
    for (int nt = 0; nt < 18; nt++) {
        int col = nt * 8 + 2 * t4;
        float2 m0 = *(const float2*)(mrow0 + col);
        float2 m1 = *(const float2*)(mrow1 + col);
        c[nt][0] = m0.x; c[nt][1] = m0.y; c[nt][2] = m1.x; c[nt][3] = m1.y;
    }

    // ---- Q A-fragments straight from GMEM (fully coalesced, zero smem) ----
    unsigned a[2][4];
    const float* q0p = base + (size_t)row0 * 384;
    const float* q1p = q0p + 8 * 384;
#pragma unroll
    for (int kt = 0; kt < 2; kt++) {
        float2 q00 = *(const float2*)(q0p + kt * 16 + 2 * t4);
        float2 q10 = *(const float2*)(q1p + kt * 16 + 2 * t4);
        float2 q01 = *(const float2*)(q0p + kt * 16 + 2 * t4 + 8);
        float2 q11 = *(const float2*)(q1p + kt * 16 + 2 * t4 + 8);
        a[kt][0] = pack_h2(q00.x * QK_SCALE, q00.y * QK_SCALE);
        a[kt][1] = pack_h2(q10.x * QK_SCALE, q10.y * QK_SCALE);
        a[kt][2] = pack_h2(q01.x * QK_SCALE, q01.y * QK_SCALE);
        a[kt][3] = pack_h2(q11.x * QK_SCALE, q11.y * QK_SCALE);
    }
    __syncthreads();

    // ---- S = mask + Q K^T  (36 mmas) ----
#pragma unroll
    for (int kt = 0; kt < 2; kt++) {
#pragma unroll
        for (int nt = 0; nt < 18; nt++) {
            const unsigned* kr = sK + (nt * 8 + g) * SKW + kt * 8;
            mma_f16(c[nt], a[kt][0], a[kt][1], a[kt][2], a[kt][3], kr[t4], kr[t4 + 4]);
        }
    }

    // ---- Softmax over 144 cols (each row in one quad) ----
    float mx0 = -1e30f, mx1 = -1e30f;
#pragma unroll
    for (int nt = 0; nt < 18; nt++) {
        mx0 = fmaxf(mx0, fmaxf(c[nt][0], c[nt][1]));
        mx1 = fmaxf(mx1, fmaxf(c[nt][2], c[nt][3]));
    }
    mx0 = fmaxf(mx0, __shfl_xor_sync(0xffffffffu, mx0, 1));
    mx0 = fmaxf(mx0, __shfl_xor_sync(0xffffffffu, mx0, 2));
    mx1 = fmaxf(mx1, __shfl_xor_sync(0xffffffffu, mx1, 1));
    mx1 = fmaxf(mx1, __shfl_xor_sync(0xffffffffu, mx1, 2));

    float s0 = 0.f, s1 = 0.f;
#pragma unroll
    for (int nt = 0; nt < 18; nt++) {
        c[nt][0] = __expf(c[nt][0] - mx0);
        c[nt][1] = __expf(c[nt][1] - mx0);
        c[nt][2] = __expf(c[nt][2] - mx1);
        c[nt][3] = __expf(c[nt][3] - mx1);
        s0 += c[nt][0] + c[nt][1];
        s1 += c[nt][2] + c[nt][3];
    }
    s0 += __shfl_xor_sync(0xffffffffu, s0, 1);
    s0 += __shfl_xor_sync(0xffffffffu, s0, 2);
    s1 += __shfl_xor_sync(0xffffffffu, s1, 1);
    s1 += __shfl_xor_sync(0xffffffffu, s1, 2);
    const float inv0 = 1.f / s0;
    const float inv1 = 1.f / s1;

    // ---- O = P V: C-frag -> fp16 A-frag by register pack (36 mmas, no smem P) ----
    float o[4][4];
#pragma unroll
    for (int nt2 = 0; nt2 < 4; nt2++) {
        o[nt2][0] = 0.f; o[nt2][1] = 0.f; o[nt2][2] = 0.f; o[nt2][3] = 0.f;
    }
#pragma unroll
    for (int j = 0; j < 9; j++) {
        unsigned pa0 = pack_h2(c[2 * j][0],     c[2 * j][1]);
        unsigned pa1 = pack_h2(c[2 * j][2],     c[2 * j][3]);
        unsigned pa2 = pack_h2(c[2 * j + 1][0], c[2 * j + 1][1]);
        unsigned pa3 = pack_h2(c[2 * j + 1][2], c[2 * j + 1][3]);
#pragma unroll
        for (int nt2 = 0; nt2 < 4; nt2++) {
            const unsigned* vr = sV + (nt2 * 8 + g) * SVW + j * 8;
            mma_f16(o[nt2], pa0, pa1, pa2, pa3, vr[t4], vr[t4 + 4]);
        }
    }

    // ---- Normalize + store: out[b, n, h*32 + d] ----
    float* obase = out + ((size_t)b * NSEQ + row0) * 128 + h * 32;
#pragma unroll
    for (int nt2 = 0; nt2 < 4; nt2++) {
        int col = nt2 * 8 + 2 * t4;
        float2 r0 = { o[nt2][0] * inv0, o[nt2][1] * inv0 };
        float2 r1 = { o[nt2][2] * inv1, o[nt2][3] * inv1 };
        *(float2*)(obase + col)           = r0;
        *(float2*)(obase + 8 * 128 + col) = r1;
    }
}

extern "C" void kernel_launch(void* const* d_in, const int* in_sizes, int n_in,
                              void* d_out, int out_size) {
    const float* qkv  = (const float*)d_in[0];
    const float* mask = (const float*)d_in[1];
    float* out = (float*)d_out;

    dim3 grid(NH, NB);
    attn144_kernel<<<grid, 288>>>(qkv, mask, out);
}

// round 10
// speedup vs baseline: 2.7693x; 1.2261x over previous
#include <cuda_runtime.h>
#include <cuda_fp16.h>
#include <cstdint>

#define NB 1024
#define NSEQ 144
#define NH 4
#define QK_SCALE 0.17677669529663687f

#define SKW 20   // K/Q row stride (f16x2 words): 16 data + 4 pad -> bank 20g+t4+8kt permutation
#define SVW 76   // V^T row stride (f16x2 words): 72 data + 4 pad -> conflict-free B-frag reads

// Mask reordered into per-fragment float4s: [h][warp][nt][lane] -> {c0,c1,c2,c3}
// 4*9*18*32 float4 = 324 KB; written once per launch by mask_transpose_kernel.
__device__ float4 g_mfrag[NH * 9 * 18 * 32];

__device__ __forceinline__ unsigned pack_h2(float lo, float hi) {
    __half2 hv = __floats2half2_rn(lo, hi);
    return *reinterpret_cast<unsigned*>(&hv);
}

__device__ __forceinline__ void mma_f16(float c[4],
                                        unsigned a0, unsigned a1, unsigned a2, unsigned a3,
                                        unsigned b0, unsigned b1) {
    asm volatile(
        "mma.sync.aligned.m16n8k16.row.col.f32.f16.f16.f32 "
        "{%0,%1,%2,%3}, {%4,%5,%6,%7}, {%8,%9}, {%0,%1,%2,%3};"
        : "+f"(c[0]), "+f"(c[1]), "+f"(c[2]), "+f"(c[3])
        : "r"(a0), "r"(a1), "r"(a2), "r"(a3), "r"(b0), "r"(b1));
}

// Reorder mask (1,4,144,144) into fragment order so the attention kernel's
// mask loads are coalesced LDG.128. Runs once per launch (~330 KB each way).
__global__ void mask_transpose_kernel(const float* __restrict__ mask) {
    int hw   = blockIdx.x;          // h*9 + w
    int h    = hw / 9;
    int w    = hw % 9;
    int nt   = threadIdx.x >> 5;    // 0..17
    int lane = threadIdx.x & 31;
    int g    = lane >> 2;
    int t4   = lane & 3;
    int row  = w * 16 + g;
    int col  = nt * 8 + 2 * t4;
    const float* m0 = mask + ((size_t)h * NSEQ + row) * NSEQ + col;
    float2 a = *(const float2*)(m0);
    float2 b = *(const float2*)(m0 + 8 * NSEQ);
    g_mfrag[(hw * 18 + nt) * 32 + lane] = make_float4(a.x, a.y, b.x, b.y);
}

// One CTA per (b,h), 2 CTAs/SM, 9 warps, warp w owns query rows [16w, 16w+16).
// fp16 mma, f32 accum. Q/K staged as f16x2 in smem (coalesced LDG.128 ->
// conflict-free LDS frags). V staged transposed. Mask loaded from the
// fragment-ordered scratch (coalesced LDG.128). P stays in registers.
__global__ __launch_bounds__(288, 2)
void attn144_kernel(const float* __restrict__ qkv,
                    float* __restrict__ out) {
    __shared__ unsigned sQ[NSEQ * SKW];   // [144][20] f16x2 (pre-scaled)
    __shared__ unsigned sK[NSEQ * SKW];   // [144][20] f16x2
    __shared__ unsigned sV[32 * SVW];     // [32][76] f16x2: word (d, key/2)

    const int h    = blockIdx.x;
    const int b    = blockIdx.y;
    const int tid  = threadIdx.x;
    const int warp = tid >> 5;
    const int lane = tid & 31;
    const int g    = lane >> 2;
    const int t4   = lane & 3;

    // qkv[b, n, j, h, d] at ((b*144+n)*384 + j*128 + h*32 + d)
    const float* base = qkv + (size_t)(b * NSEQ) * 384 + h * 32;

    // ---- Stage Q (scaled), K (f16x2 along d) and V^T (f16x2 along keys) ----
#pragma unroll
    for (int it = 0; it < 4; it++) {
        int idx = tid + it * 288;
        int row = idx >> 3;          // seq index
        int d4  = (idx & 7) * 4;     // head-dim base
        const float* p = base + (size_t)row * 384 + d4;
        float4 q4 = *(const float4*)(p);
        float4 k4 = *(const float4*)(p + 128);
        float4 v4 = *(const float4*)(p + 256);

        unsigned q01 = pack_h2(q4.x * QK_SCALE, q4.y * QK_SCALE);
        unsigned q23 = pack_h2(q4.z * QK_SCALE, q4.w * QK_SCALE);
        *(uint2*)(sQ + row * SKW + (d4 >> 1)) = make_uint2(q01, q23);

        unsigned k01 = pack_h2(k4.x, k4.y);
        unsigned k23 = pack_h2(k4.z, k4.w);
        *(uint2*)(sK + row * SKW + (d4 >> 1)) = make_uint2(k01, k23);

        unsigned v01 = pack_h2(v4.x, v4.y);
        unsigned v23 = pack_h2(v4.z, v4.w);
        // partner lane (^8) holds key^1 at same d4
        unsigned pv01 = __shfl_xor_sync(0xffffffffu, v01, 8);
        unsigned pv23 = __shfl_xor_sync(0xffffffffu, v23, 8);
        int kw = row >> 1;
        if (!(idx & 8)) {  // even key: I am the lo half of each pair
            sV[(d4    ) * SVW + kw] = __byte_perm(v01, pv01, 0x5410);
            sV[(d4 + 1) * SVW + kw] = __byte_perm(v01, pv01, 0x7632);
        } else {           // odd key: partner (even key) is the lo half
            sV[(d4 + 2) * SVW + kw] = __byte_perm(pv23, v23, 0x5410);
            sV[(d4 + 3) * SVW + kw] = __byte_perm(pv23, v23, 0x7632);
        }
    }

    const int row0 = warp * 16 + g;

    // ---- Mask -> S accumulators, coalesced LDG.128 (overlaps staging) ----
    float c[18][4];
    const float4* mf = g_mfrag + ((h * 9 + warp) * 18) * 32 + lane;
#pragma unroll
    for (int nt = 0; nt < 18; nt++) {
        float4 m = mf[nt * 32];
        c[nt][0] = m.x; c[nt][1] = m.y; c[nt][2] = m.z; c[nt][3] = m.w;
    }
    __syncthreads();

    // ---- Q A-fragments from smem (conflict-free) ----
    unsigned a[2][4];
#pragma unroll
    for (int kt = 0; kt < 2; kt++) {
        const unsigned* q0 = sQ + row0 * SKW + kt * 8;
        const unsigned* q1 = sQ + (row0 + 8) * SKW + kt * 8;
        a[kt][0] = q0[t4];
        a[kt][1] = q1[t4];
        a[kt][2] = q0[t4 + 4];
        a[kt][3] = q1[t4 + 4];
    }

    // ---- S = mask + Q K^T  (36 mmas) ----
#pragma unroll
    for (int kt = 0; kt < 2; kt++) {
#pragma unroll
        for (int nt = 0; nt < 18; nt++) {
            const unsigned* kr = sK + (nt * 8 + g) * SKW + kt * 8;
            mma_f16(c[nt], a[kt][0], a[kt][1], a[kt][2], a[kt][3], kr[t4], kr[t4 + 4]);
        }
    }

    // ---- Softmax over 144 cols (each row in one quad) ----
    float mx0 = -1e30f, mx1 = -1e30f;
#pragma unroll
    for (int nt = 0; nt < 18; nt++) {
        mx0 = fmaxf(mx0, fmaxf(c[nt][0], c[nt][1]));
        mx1 = fmaxf(mx1, fmaxf(c[nt][2], c[nt][3]));
    }
    mx0 = fmaxf(mx0, __shfl_xor_sync(0xffffffffu, mx0, 1));
    mx0 = fmaxf(mx0, __shfl_xor_sync(0xffffffffu, mx0, 2));
    mx1 = fmaxf(mx1, __shfl_xor_sync(0xffffffffu, mx1, 1));
    mx1 = fmaxf(mx1, __shfl_xor_sync(0xffffffffu, mx1, 2));

    float s0 = 0.f, s1 = 0.f;
#pragma unroll
    for (int nt = 0; nt < 18; nt++) {
        c[nt][0] = __expf(c[nt][0] - mx0);
        c[nt][1] = __expf(c[nt][1] - mx0);
        c[nt][2] = __expf(c[nt][2] - mx1);
        c[nt][3] = __expf(c[nt][3] - mx1);
        s0 += c[nt][0] + c[nt][1];
        s1 += c[nt][2] + c[nt][3];
    }
    s0 += __shfl_xor_sync(0xffffffffu, s0, 1);
    s0 += __shfl_xor_sync(0xffffffffu, s0, 2);
    s1 += __shfl_xor_sync(0xffffffffu, s1, 1);
    s1 += __shfl_xor_sync(0xffffffffu, s1, 2);
    const float inv0 = 1.f / s0;
    const float inv1 = 1.f / s1;

    // ---- O = P V: C-frag -> fp16 A-frag by register pack (36 mmas, no smem P) ----
    float o[4][4];
#pragma unroll
    for (int nt2 = 0; nt2 < 4; nt2++) {
        o[nt2][0] = 0.f; o[nt2][1] = 0.f; o[nt2][2] = 0.f; o[nt2][3] = 0.f;
    }
#pragma unroll
    for (int j = 0; j < 9; j++) {
        unsigned pa0 = pack_h2(c[2 * j][0],     c[2 * j][1]);
        unsigned pa1 = pack_h2(c[2 * j][2],     c[2 * j][3]);
        unsigned pa2 = pack_h2(c[2 * j + 1][0], c[2 * j + 1][1]);
        unsigned pa3 = pack_h2(c[2 * j + 1][2], c[2 * j + 1][3]);
#pragma unroll
        for (int nt2 = 0; nt2 < 4; nt2++) {
            const unsigned* vr = sV + (nt2 * 8 + g) * SVW + j * 8;
            mma_f16(o[nt2], pa0, pa1, pa2, pa3, vr[t4], vr[t4 + 4]);
        }
    }

    // ---- Normalize + store: out[b, n, h*32 + d] ----
    float* obase = out + ((size_t)b * NSEQ + row0) * 128 + h * 32;
#pragma unroll
    for (int nt2 = 0; nt2 < 4; nt2++) {
        int col = nt2 * 8 + 2 * t4;
        float2 r0 = { o[nt2][0] * inv0, o[nt2][1] * inv0 };
        float2 r1 = { o[nt2][2] * inv1, o[nt2][3] * inv1 };
        *(float2*)(obase + col)           = r0;
        *(float2*)(obase + 8 * 128 + col) = r1;
    }
}

extern "C" void kernel_launch(void* const* d_in, const int* in_sizes, int n_in,
                              void* d_out, int out_size) {
    const float* qkv  = (const float*)d_in[0];
    const float* mask = (const float*)d_in[1];
    float* out = (float*)d_out;

    mask_transpose_kernel<<<NH * 9, 18 * 32>>>(mask);

    dim3 grid(NH, NB);
    attn144_kernel<<<grid, 288>>>(qkv, out);
}

// round 11
// speedup vs baseline: 2.9093x; 1.0505x over previous
#include <cuda_runtime.h>
#include <cuda_fp16.h>
#include <cstdint>

#define NB 1024
#define NSEQ 144
#define NH 4
#define QK_SCALE 0.17677669529663687f

#define SKW 20   // K/Q row stride (f16x2 words): conflict-free frag reads
#define SVW 76   // V^T row stride (f16x2 words): conflict-free B-frag reads
#define SOW 40   // out-transpose row stride (floats): conflict-free STS.64/LDS.128

// smem layout (32-bit words)
#define OFF_Q 0                       // [144][20]
#define OFF_K (OFF_Q + NSEQ * SKW)    // [144][20]
#define OFF_V (OFF_K + NSEQ * SKW)    // [32][76]
#define OFF_O (OFF_V + 32 * SVW)      // [9][16][40] floats
#define SMEM_WORDS (OFF_O + 9 * 16 * SOW)   // 13952 words = 55808 B

// Mask reordered into per-fragment f16x2 pairs: [h][warp][nt][lane] -> {h2(c0,c1), h2(c2,c3)}
__device__ uint2 g_mfrag[NH * 9 * 18 * 32];   // 162 KB, L2-resident

__device__ __forceinline__ unsigned pack_h2(float lo, float hi) {
    __half2 hv = __floats2half2_rn(lo, hi);
    return *reinterpret_cast<unsigned*>(&hv);
}

__device__ __forceinline__ void mma_f16(float c[4],
                                        unsigned a0, unsigned a1, unsigned a2, unsigned a3,
                                        unsigned b0, unsigned b1) {
    asm volatile(
        "mma.sync.aligned.m16n8k16.row.col.f32.f16.f16.f32 "
        "{%0,%1,%2,%3}, {%4,%5,%6,%7}, {%8,%9}, {%0,%1,%2,%3};"
        : "+f"(c[0]), "+f"(c[1]), "+f"(c[2]), "+f"(c[3])
        : "r"(a0), "r"(a1), "r"(a2), "r"(a3), "r"(b0), "r"(b1));
}

// Reorder mask (1,4,144,144) into fp16 fragment order (coalesced LDG.64 in main kernel).
__global__ void mask_transpose_kernel(const float* __restrict__ mask) {
    int hw   = blockIdx.x;          // h*9 + w
    int h    = hw / 9;
    int w    = hw % 9;
    int nt   = threadIdx.x >> 5;    // 0..17
    int lane = threadIdx.x & 31;
    int g    = lane >> 2;
    int t4   = lane & 3;
    int row  = w * 16 + g;
    int col  = nt * 8 + 2 * t4;
    const float* m0 = mask + ((size_t)h * NSEQ + row) * NSEQ + col;
    float2 a = *(const float2*)(m0);
    float2 b = *(const float2*)(m0 + 8 * NSEQ);
    g_mfrag[(hw * 18 + nt) * 32 + lane] = make_uint2(pack_h2(a.x, a.y), pack_h2(b.x, b.y));
}

// One CTA per (b,h), 2 CTAs/SM, 9 warps, warp w owns query rows [16w, 16w+16).
// fp16 mma, f32 accum. Q/K staged f16x2 in smem, V staged transposed,
// mask from fp16 fragment scratch, P in registers,
// output through a per-warp smem transpose -> line-minimal STG.128.
__global__ __launch_bounds__(288, 2)
void attn144_kernel(const float* __restrict__ qkv,
                    float* __restrict__ out) {
    extern __shared__ unsigned smem[];
    unsigned* sQ = smem + OFF_Q;
    unsigned* sK = smem + OFF_K;
    unsigned* sV = smem + OFF_V;
    float*    sO = (float*)(smem + OFF_O);

    const int h    = blockIdx.x;
    const int b    = blockIdx.y;
    const int tid  = threadIdx.x;
    const int warp = tid >> 5;
    const int lane = tid & 31;
    const int g    = lane >> 2;
    const int t4   = lane & 3;

    // qkv[b, n, j, h, d] at ((b*144+n)*384 + j*128 + h*32 + d)
    const float* base = qkv + (size_t)(b * NSEQ) * 384 + h * 32;

    // ---- Stage Q (scaled), K (f16x2 along d) and V^T (f16x2 along keys) ----
#pragma unroll
    for (int it = 0; it < 4; it++) {
        int idx = tid + it * 288;
        int row = idx >> 3;          // seq index
        int d4  = (idx & 7) * 4;     // head-dim base
        const float* p = base + (size_t)row * 384 + d4;
        float4 q4 = *(const float4*)(p);
        float4 k4 = *(const float4*)(p + 128);
        float4 v4 = *(const float4*)(p + 256);

        unsigned q01 = pack_h2(q4.x * QK_SCALE, q4.y * QK_SCALE);
        unsigned q23 = pack_h2(q4.z * QK_SCALE, q4.w * QK_SCALE);
        *(uint2*)(sQ + row * SKW + (d4 >> 1)) = make_uint2(q01, q23);

        unsigned k01 = pack_h2(k4.x, k4.y);
        unsigned k23 = pack_h2(k4.z, k4.w);
        *(uint2*)(sK + row * SKW + (d4 >> 1)) = make_uint2(k01, k23);

        unsigned v01 = pack_h2(v4.x, v4.y);
        unsigned v23 = pack_h2(v4.z, v4.w);
        // partner lane (^8) holds key^1 at same d4
        unsigned pv01 = __shfl_xor_sync(0xffffffffu, v01, 8);
        unsigned pv23 = __shfl_xor_sync(0xffffffffu, v23, 8);
        int kw = row >> 1;
        if (!(idx & 8)) {  // even key: I am the lo half of each pair
            sV[(d4    ) * SVW + kw] = __byte_perm(v01, pv01, 0x5410);
            sV[(d4 + 1) * SVW + kw] = __byte_perm(v01, pv01, 0x7632);
        } else {           // odd key: partner (even key) is the lo half
            sV[(d4 + 2) * SVW + kw] = __byte_perm(pv23, v23, 0x5410);
            sV[(d4 + 3) * SVW + kw] = __byte_perm(pv23, v23, 0x7632);
        }
    }

    const int row0 = warp * 16 + g;

    // ---- Mask (fp16 frags) -> S accumulators, coalesced LDG.64 ----
    float c[18][4];
    const uint2* mf = g_mfrag + ((h * 9 + warp) * 18) * 32 + lane;
#pragma unroll
    for (int nt = 0; nt < 18; nt++) {
        uint2 mh = mf[nt * 32];
        float2 f0 = __half22float2(*reinterpret_cast<__half2*>(&mh.x));
        float2 f1 = __half22float2(*reinterpret_cast<__half2*>(&mh.y));
        c[nt][0] = f0.x; c[nt][1] = f0.y; c[nt][2] = f1.x; c[nt][3] = f1.y;
    }
    __syncthreads();

    // ---- Q A-fragments from smem (conflict-free) ----
    unsigned a[2][4];
#pragma unroll
    for (int kt = 0; kt < 2; kt++) {
        const unsigned* q0 = sQ + row0 * SKW + kt * 8;
        const unsigned* q1 = sQ + (row0 + 8) * SKW + kt * 8;
        a[kt][0] = q0[t4];
        a[kt][1] = q1[t4];
        a[kt][2] = q0[t4 + 4];
        a[kt][3] = q1[t4 + 4];
    }

    // ---- S = mask + Q K^T  (36 mmas) ----
#pragma unroll
    for (int kt = 0; kt < 2; kt++) {
#pragma unroll
        for (int nt = 0; nt < 18; nt++) {
            const unsigned* kr = sK + (nt * 8 + g) * SKW + kt * 8;
            mma_f16(c[nt], a[kt][0], a[kt][1], a[kt][2], a[kt][3], kr[t4], kr[t4 + 4]);
        }
    }

    // ---- Softmax over 144 cols (each row in one quad) ----
    float mx0 = -1e30f, mx1 = -1e30f;
#pragma unroll
    for (int nt = 0; nt < 18; nt++) {
        mx0 = fmaxf(mx0, fmaxf(c[nt][0], c[nt][1]));
        mx1 = fmaxf(mx1, fmaxf(c[nt][2], c[nt][3]));
    }
    mx0 = fmaxf(mx0, __shfl_xor_sync(0xffffffffu, mx0, 1));
    mx0 = fmaxf(mx0, __shfl_xor_sync(0xffffffffu, mx0, 2));
    mx1 = fmaxf(mx1, __shfl_xor_sync(0xffffffffu, mx1, 1));
    mx1 = fmaxf(mx1, __shfl_xor_sync(0xffffffffu, mx1, 2));

    float s0 = 0.f, s1 = 0.f;
#pragma unroll
    for (int nt = 0; nt < 18; nt++) {
        c[nt][0] = __expf(c[nt][0] - mx0);
        c[nt][1] = __expf(c[nt][1] - mx0);
        c[nt][2] = __expf(c[nt][2] - mx1);
        c[nt][3] = __expf(c[nt][3] - mx1);
        s0 += c[nt][0] + c[nt][1];
        s1 += c[nt][2] + c[nt][3];
    }
    s0 += __shfl_xor_sync(0xffffffffu, s0, 1);
    s0 += __shfl_xor_sync(0xffffffffu, s0, 2);
    s1 += __shfl_xor_sync(0xffffffffu, s1, 1);
    s1 += __shfl_xor_sync(0xffffffffu, s1, 2);
    const float inv0 = 1.f / s0;
    const float inv1 = 1.f / s1;

    // ---- O = P V: C-frag -> fp16 A-frag by register pack (36 mmas, no smem P) ----
    float o[4][4];
#pragma unroll
    for (int nt2 = 0; nt2 < 4; nt2++) {
        o[nt2][0] = 0.f; o[nt2][1] = 0.f; o[nt2][2] = 0.f; o[nt2][3] = 0.f;
    }
#pragma unroll
    for (int j = 0; j < 9; j++) {
        unsigned pa0 = pack_h2(c[2 * j][0],     c[2 * j][1]);
        unsigned pa1 = pack_h2(c[2 * j][2],     c[2 * j][3]);
        unsigned pa2 = pack_h2(c[2 * j + 1][0], c[2 * j + 1][1]);
        unsigned pa3 = pack_h2(c[2 * j + 1][2], c[2 * j + 1][3]);
#pragma unroll
        for (int nt2 = 0; nt2 < 4; nt2++) {
            const unsigned* vr = sV + (nt2 * 8 + g) * SVW + j * 8;
            mma_f16(o[nt2], pa0, pa1, pa2, pa3, vr[t4], vr[t4 + 4]);
        }
    }

    // ---- Normalize -> per-warp smem transpose -> line-minimal coalesced store ----
    float* so = sO + warp * 16 * SOW;
#pragma unroll
    for (int nt2 = 0; nt2 < 4; nt2++) {
        int col = nt2 * 8 + 2 * t4;
        *(float2*)(so + g * SOW + col)       = make_float2(o[nt2][0] * inv0, o[nt2][1] * inv0);
        *(float2*)(so + (g + 8) * SOW + col) = make_float2(o[nt2][2] * inv1, o[nt2][3] * inv1);
    }
    __syncwarp();

    // out[b, n, h*32 + d]; warp covers 4 full rows (4 x 128B lines) per STG.128
    const int rsub = lane >> 3;          // 0..3
    const int cw   = (lane & 7) * 4;     // 0,4,...,28
    float* ob = out + ((size_t)b * NSEQ + warp * 16 + rsub) * 128 + h * 32 + cw;
#pragma unroll
    for (int it = 0; it < 4; it++) {
        int r = it * 4 + rsub;
        float4 val = *(float4*)(so + r * SOW + cw);
        *(float4*)(ob + (size_t)it * 4 * 128) = val;
    }
}

extern "C" void kernel_launch(void* const* d_in, const int* in_sizes, int n_in,
                              void* d_out, int out_size) {
    const float* qkv  = (const float*)d_in[0];
    const float* mask = (const float*)d_in[1];
    float* out = (float*)d_out;

    mask_transpose_kernel<<<NH * 9, 18 * 32>>>(mask);

    const int smem_bytes = SMEM_WORDS * 4;   // 55,808 B
    cudaFuncSetAttribute(attn144_kernel,
                         cudaFuncAttributeMaxDynamicSharedMemorySize, smem_bytes);

    dim3 grid(NH, NB);
    attn144_kernel<<<grid, 288, smem_bytes>>>(qkv, out);
}

// round 12
// speedup vs baseline: 3.0680x; 1.0546x over previous
#include <cuda_runtime.h>
#include <cuda_fp16.h>
#include <cstdint>

#define NB 1024
#define NSEQ 144
#define NH 4
// qk scale * log2(e): softmax computed in base-2 (exp2), monotone-equivalent
#define QK_SCALE_L2E (0.17677669529663687f * 1.4426950408889634f)
#define LOG2E 1.4426950408889634f

#define SKW 20   // K/Q row stride (f16x2 words): conflict-free frag reads
#define SVW 76   // V^T row stride (f16x2 words): conflict-free B-frag reads
#define SOW 40   // out-transpose row stride (floats): conflict-free STS.64/LDS.128

// smem layout (32-bit words)
#define OFF_Q 0                       // [144][20]
#define OFF_K (OFF_Q + NSEQ * SKW)    // [144][20]
#define OFF_V (OFF_K + NSEQ * SKW)    // [32][76]
#define OFF_O (OFF_V + 32 * SVW)      // [9][16][40] floats
#define SMEM_WORDS (OFF_O + 9 * 16 * SOW)   // 13952 words = 55808 B

// Mask (x log2e) in fp16 fragment order: [h][warp][nt][lane] -> {h2(c0,c1), h2(c2,c3)}
__device__ uint2 g_mfrag[NH * 9 * 18 * 32];   // 162 KB, L2-resident

__device__ __forceinline__ unsigned pack_h2(float lo, float hi) {
    __half2 hv = __floats2half2_rn(lo, hi);
    return *reinterpret_cast<unsigned*>(&hv);
}

__device__ __forceinline__ float ex2(float x) {
    float r;
    asm("ex2.approx.f32 %0, %1;" : "=f"(r) : "f"(x));
    return r;
}

__device__ __forceinline__ void mma_f16(float c[4],
                                        unsigned a0, unsigned a1, unsigned a2, unsigned a3,
                                        unsigned b0, unsigned b1) {
    asm volatile(
        "mma.sync.aligned.m16n8k16.row.col.f32.f16.f16.f32 "
        "{%0,%1,%2,%3}, {%4,%5,%6,%7}, {%8,%9}, {%0,%1,%2,%3};"
        : "+f"(c[0]), "+f"(c[1]), "+f"(c[2]), "+f"(c[3])
        : "r"(a0), "r"(a1), "r"(a2), "r"(a3), "r"(b0), "r"(b1));
}

// Reorder mask (1,4,144,144) into fp16 fragment order, scaled by log2e.
__global__ void mask_transpose_kernel(const float* __restrict__ mask) {
    int hw   = blockIdx.x;          // h*9 + w
    int h    = hw / 9;
    int w    = hw % 9;
    int nt   = threadIdx.x >> 5;    // 0..17
    int lane = threadIdx.x & 31;
    int g    = lane >> 2;
    int t4   = lane & 3;
    int row  = w * 16 + g;
    int col  = nt * 8 + 2 * t4;
    const float* m0 = mask + ((size_t)h * NSEQ + row) * NSEQ + col;
    float2 a = *(const float2*)(m0);
    float2 b = *(const float2*)(m0 + 8 * NSEQ);
    g_mfrag[(hw * 18 + nt) * 32 + lane] =
        make_uint2(pack_h2(a.x * LOG2E, a.y * LOG2E),
                   pack_h2(b.x * LOG2E, b.y * LOG2E));
}

// One CTA per (b,h), 3 CTAs/SM, 9 warps, warp w owns query rows [16w, 16w+16).
// Online (flash) softmax over 3 chunks of 48 key columns: shrinks the S
// accumulator from 72 to 24 regs so 3 CTAs fit the regfile.
// fp16 mma, f32 accum; base-2 softmax (scales pre-multiplied by log2e).
__global__ __launch_bounds__(288, 3)
void attn144_kernel(const float* __restrict__ qkv,
                    float* __restrict__ out) {
    extern __shared__ unsigned smem[];
    unsigned* sQ = smem + OFF_Q;
    unsigned* sK = smem + OFF_K;
    unsigned* sV = smem + OFF_V;
    float*    sO = (float*)(smem + OFF_O);

    const int h    = blockIdx.x;
    const int b    = blockIdx.y;
    const int tid  = threadIdx.x;
    const int warp = tid >> 5;
    const int lane = tid & 31;
    const int g    = lane >> 2;
    const int t4   = lane & 3;

    // qkv[b, n, j, h, d] at ((b*144+n)*384 + j*128 + h*32 + d)
    const float* base = qkv + (size_t)(b * NSEQ) * 384 + h * 32;

    // ---- Stage Q (scaled by qk_scale*log2e), K, V^T (f16x2) ----
#pragma unroll
    for (int it = 0; it < 4; it++) {
        int idx = tid + it * 288;
        int row = idx >> 3;          // seq index
        int d4  = (idx & 7) * 4;     // head-dim base
        const float* p = base + (size_t)row * 384 + d4;
        float4 q4 = *(const float4*)(p);
        float4 k4 = *(const float4*)(p + 128);
        float4 v4 = *(const float4*)(p + 256);

        unsigned q01 = pack_h2(q4.x * QK_SCALE_L2E, q4.y * QK_SCALE_L2E);
        unsigned q23 = pack_h2(q4.z * QK_SCALE_L2E, q4.w * QK_SCALE_L2E);
        *(uint2*)(sQ + row * SKW + (d4 >> 1)) = make_uint2(q01, q23);

        unsigned k01 = pack_h2(k4.x, k4.y);
        unsigned k23 = pack_h2(k4.z, k4.w);
        *(uint2*)(sK + row * SKW + (d4 >> 1)) = make_uint2(k01, k23);

        unsigned v01 = pack_h2(v4.x, v4.y);
        unsigned v23 = pack_h2(v4.z, v4.w);
        // partner lane (^8) holds key^1 at same d4
        unsigned pv01 = __shfl_xor_sync(0xffffffffu, v01, 8);
        unsigned pv23 = __shfl_xor_sync(0xffffffffu, v23, 8);
        int kw = row >> 1;
        if (!(idx & 8)) {  // even key: I am the lo half of each pair
            sV[(d4    ) * SVW + kw] = __byte_perm(v01, pv01, 0x5410);
            sV[(d4 + 1) * SVW + kw] = __byte_perm(v01, pv01, 0x7632);
        } else {           // odd key: partner (even key) is the lo half
            sV[(d4 + 2) * SVW + kw] = __byte_perm(pv23, v23, 0x5410);
            sV[(d4 + 3) * SVW + kw] = __byte_perm(pv23, v23, 0x7632);
        }
    }

    const int row0 = warp * 16 + g;
    const uint2* mf = g_mfrag + ((h * 9 + warp) * 18) * 32 + lane;
    __syncthreads();

    // ---- Q A-fragments from smem (conflict-free), reused by all chunks ----
    unsigned a[2][4];
#pragma unroll
    for (int kt = 0; kt < 2; kt++) {
        const unsigned* q0 = sQ + row0 * SKW + kt * 8;
        const unsigned* q1 = sQ + (row0 + 8) * SKW + kt * 8;
        a[kt][0] = q0[t4];
        a[kt][1] = q1[t4];
        a[kt][2] = q0[t4 + 4];
        a[kt][3] = q1[t4 + 4];
    }

    // ---- Online softmax state ----
    float m0 = -1e30f, m1 = -1e30f;   // running max (base-2 logits)
    float l0 = 0.f,    l1 = 0.f;      // running per-lane partial sums
    float o[4][4];
#pragma unroll
    for (int nt2 = 0; nt2 < 4; nt2++) {
        o[nt2][0] = 0.f; o[nt2][1] = 0.f; o[nt2][2] = 0.f; o[nt2][3] = 0.f;
    }

#pragma unroll
    for (int ch = 0; ch < 3; ch++) {
        // S chunk = mask + Q K^T over 48 key cols (6 n-tiles)
        float c[6][4];
#pragma unroll
        for (int j = 0; j < 6; j++) {
            uint2 mh = mf[(ch * 6 + j) * 32];
            float2 f0 = __half22float2(*reinterpret_cast<__half2*>(&mh.x));
            float2 f1 = __half22float2(*reinterpret_cast<__half2*>(&mh.y));
            c[j][0] = f0.x; c[j][1] = f0.y; c[j][2] = f1.x; c[j][3] = f1.y;
        }
#pragma unroll
        for (int kt = 0; kt < 2; kt++) {
#pragma unroll
            for (int j = 0; j < 6; j++) {
                const unsigned* kr = sK + (ch * 48 + j * 8 + g) * SKW + kt * 8;
                mma_f16(c[j], a[kt][0], a[kt][1], a[kt][2], a[kt][3],
                        kr[t4], kr[t4 + 4]);
            }
        }

        // chunk max (quad-reduced), rescale factors
        float cm0 = -1e30f, cm1 = -1e30f;
#pragma unroll
        for (int j = 0; j < 6; j++) {
            cm0 = fmaxf(cm0, fmaxf(c[j][0], c[j][1]));
            cm1 = fmaxf(cm1, fmaxf(c[j][2], c[j][3]));
        }
        cm0 = fmaxf(cm0, __shfl_xor_sync(0xffffffffu, cm0, 1));
        cm0 = fmaxf(cm0, __shfl_xor_sync(0xffffffffu, cm0, 2));
        cm1 = fmaxf(cm1, __shfl_xor_sync(0xffffffffu, cm1, 1));
        cm1 = fmaxf(cm1, __shfl_xor_sync(0xffffffffu, cm1, 2));
        float nm0 = fmaxf(m0, cm0), nm1 = fmaxf(m1, cm1);
        float f0 = ex2(m0 - nm0),   f1 = ex2(m1 - nm1);
        m0 = nm0; m1 = nm1;

        // exp2 + per-lane partial sums, rescale running state
        float s0 = 0.f, s1 = 0.f;
#pragma unroll
        for (int j = 0; j < 6; j++) {
            c[j][0] = ex2(c[j][0] - m0);
            c[j][1] = ex2(c[j][1] - m0);
            c[j][2] = ex2(c[j][2] - m1);
            c[j][3] = ex2(c[j][3] - m1);
            s0 += c[j][0] + c[j][1];
            s1 += c[j][2] + c[j][3];
        }
        l0 = l0 * f0 + s0;
        l1 = l1 * f1 + s1;
#pragma unroll
        for (int nt2 = 0; nt2 < 4; nt2++) {
            o[nt2][0] *= f0; o[nt2][1] *= f0;
            o[nt2][2] *= f1; o[nt2][3] *= f1;
        }

        // O += P_chunk * V_chunk  (C-frag -> fp16 A-frag register pack)
#pragma unroll
        for (int j2 = 0; j2 < 3; j2++) {
            unsigned pa0 = pack_h2(c[2 * j2][0],     c[2 * j2][1]);
            unsigned pa1 = pack_h2(c[2 * j2][2],     c[2 * j2][3]);
            unsigned pa2 = pack_h2(c[2 * j2 + 1][0], c[2 * j2 + 1][1]);
            unsigned pa3 = pack_h2(c[2 * j2 + 1][2], c[2 * j2 + 1][3]);
            int jj = ch * 3 + j2;
#pragma unroll
            for (int nt2 = 0; nt2 < 4; nt2++) {
                const unsigned* vr = sV + (nt2 * 8 + g) * SVW + jj * 8;
                mma_f16(o[nt2], pa0, pa1, pa2, pa3, vr[t4], vr[t4 + 4]);
            }
        }
    }

    // ---- Final row-sum reduce + normalize ----
    l0 += __shfl_xor_sync(0xffffffffu, l0, 1);
    l0 += __shfl_xor_sync(0xffffffffu, l0, 2);
    l1 += __shfl_xor_sync(0xffffffffu, l1, 1);
    l1 += __shfl_xor_sync(0xffffffffu, l1, 2);
    const float inv0 = 1.f / l0;
    const float inv1 = 1.f / l1;

    // ---- Normalize -> per-warp smem transpose -> line-minimal coalesced store ----
    float* so = sO + warp * 16 * SOW;
#pragma unroll
    for (int nt2 = 0; nt2 < 4; nt2++) {
        int col = nt2 * 8 + 2 * t4;
        *(float2*)(so + g * SOW + col)       = make_float2(o[nt2][0] * inv0, o[nt2][1] * inv0);
        *(float2*)(so + (g + 8) * SOW + col) = make_float2(o[nt2][2] * inv1, o[nt2][3] * inv1);
    }
    __syncwarp();

    // out[b, n, h*32 + d]; warp covers 4 full rows (4 x 128B lines) per STG.128
    const int rsub = lane >> 3;          // 0..3
    const int cw   = (lane & 7) * 4;     // 0,4,...,28
    float* ob = out + ((size_t)b * NSEQ + warp * 16 + rsub) * 128 + h * 32 + cw;
#pragma unroll
    for (int it = 0; it < 4; it++) {
        int r = it * 4 + rsub;
        float4 val = *(float4*)(so + r * SOW + cw);
        *(float4*)(ob + (size_t)it * 4 * 128) = val;
    }
}

extern "C" void kernel_launch(void* const* d_in, const int* in_sizes, int n_in,
                              void* d_out, int out_size) {
    const float* qkv  = (const float*)d_in[0];
    const float* mask = (const float*)d_in[1];
    float* out = (float*)d_out;

    mask_transpose_kernel<<<NH * 9, 18 * 32>>>(mask);

    const int smem_bytes = SMEM_WORDS * 4;   // 55,808 B
    cudaFuncSetAttribute(attn144_kernel,
                         cudaFuncAttributeMaxDynamicSharedMemorySize, smem_bytes);

    dim3 grid(NH, NB);
    attn144_kernel<<<grid, 288, smem_bytes>>>(qkv, out);
}